// round 2
// baseline (speedup 1.0000x reference)
#include <cuda_runtime.h>
#include <cuda_bf16.h>

// GCN 2-layer: N=100000 nodes, E=3200000 edges, 25 -> 16 -> 2, log_softmax.
// out = D^-1/2 (A+I) D^-1/2 (X W) + b per layer.
// Rewrite: g = dinv * (x@W);  out[i] = dinv[i]*(sum_{j->i} g[j] + g[i]) + b.
// NOTE: edge_index is int32 on device (JAX x64 disabled downcasts int64->int32).

#define NMAX   100000
#define F_IN   25
#define F_HID  16
#define F_OUT  2

// ---- scratch (device globals; no allocation allowed) ----
__device__ int   d_deg [NMAX];
__device__ float d_dinv[NMAX];
__device__ float d_g1  [NMAX * F_HID];
__device__ float d_agg1[NMAX * F_HID];
__device__ float d_g2  [NMAX * F_OUT];
__device__ float d_agg2[NMAX * F_OUT];

// ---- kernels ----

__global__ void k_zero(int n) {
    int i = blockIdx.x * blockDim.x + threadIdx.x;
    if (i >= n) return;
    d_deg[i] = 0;
#pragma unroll
    for (int f = 0; f < F_HID; f++) d_agg1[i * F_HID + f] = 0.0f;
    d_agg2[i * 2 + 0] = 0.0f;
    d_agg2[i * 2 + 1] = 0.0f;
}

__global__ void k_deg(const int* __restrict__ col, int n_edges, int n_nodes) {
    int i = blockIdx.x * blockDim.x + threadIdx.x;
    if (i >= n_edges) return;
    unsigned t = (unsigned)__ldg(&col[i]);
    if (t < (unsigned)n_nodes) atomicAdd(&d_deg[t], 1);
}

// dinv = rsqrt(deg_in + 1 self-loop); g1 = dinv * (x @ W1)
__global__ void k_node1(const float* __restrict__ x,
                        const float* __restrict__ W1, int n) {
    __shared__ float sW[F_IN * F_HID];
    for (int i = threadIdx.x; i < F_IN * F_HID; i += blockDim.x)
        sW[i] = W1[i];
    __syncthreads();

    int i = blockIdx.x * blockDim.x + threadIdx.x;
    if (i >= n) return;

    float xv[F_IN];
#pragma unroll
    for (int k = 0; k < F_IN; k++) xv[k] = x[i * F_IN + k];

    float dinv = rsqrtf((float)(d_deg[i] + 1));
    d_dinv[i] = dinv;

#pragma unroll
    for (int f = 0; f < F_HID; f++) {
        float s = 0.0f;
#pragma unroll
        for (int k = 0; k < F_IN; k++) s += xv[k] * sW[k * F_HID + f];
        d_g1[i * F_HID + f] = dinv * s;
    }
}

// Layer-1 scatter: 4 threads per edge, each moves a float4 with vector red.
__global__ void k_sc1(const int* __restrict__ row,
                      const int* __restrict__ col, int n_edges, int n_nodes) {
    int gid = blockIdx.x * blockDim.x + threadIdx.x;
    int e = gid >> 2;
    int c = gid & 3;
    if (e >= n_edges) return;
    unsigned r = (unsigned)__ldg(&row[e]);
    unsigned t = (unsigned)__ldg(&col[e]);
    if (r >= (unsigned)n_nodes || t >= (unsigned)n_nodes) return;
    float4 v = *reinterpret_cast<const float4*>(&d_g1[r * F_HID + c * 4]);
    float* dst = &d_agg1[t * F_HID + c * 4];
    asm volatile("red.global.add.v4.f32 [%0], {%1,%2,%3,%4};"
                 :: "l"(dst), "f"(v.x), "f"(v.y), "f"(v.z), "f"(v.w)
                 : "memory");
}

// Epilogue-1 + layer-2 transform: t = relu(dinv*(agg1+g1)+b1); g2 = dinv*(t@W2)
__global__ void k_node2(const float* __restrict__ b1,
                        const float* __restrict__ W2, int n) {
    __shared__ float sb1[F_HID];
    __shared__ float sW2[F_HID * F_OUT];
    if (threadIdx.x < F_HID) sb1[threadIdx.x] = b1[threadIdx.x];
    if (threadIdx.x < F_HID * F_OUT) sW2[threadIdx.x] = W2[threadIdx.x];
    __syncthreads();

    int i = blockIdx.x * blockDim.x + threadIdx.x;
    if (i >= n) return;

    float dinv = d_dinv[i];
    float h0 = 0.0f, h1v = 0.0f;
#pragma unroll
    for (int f = 0; f < F_HID; f += 4) {
        float4 a = *reinterpret_cast<const float4*>(&d_agg1[i * F_HID + f]);
        float4 g = *reinterpret_cast<const float4*>(&d_g1[i * F_HID + f]);
        float tv[4] = {a.x + g.x, a.y + g.y, a.z + g.z, a.w + g.w};
#pragma unroll
        for (int j = 0; j < 4; j++) {
            float tt = fmaxf(dinv * tv[j] + sb1[f + j], 0.0f);
            h0 += tt * sW2[(f + j) * F_OUT + 0];
            h1v += tt * sW2[(f + j) * F_OUT + 1];
        }
    }
    d_g2[i * 2 + 0] = dinv * h0;
    d_g2[i * 2 + 1] = dinv * h1v;
}

// Layer-2 scatter: 1 thread per edge, float2 vector red.
__global__ void k_sc2(const int* __restrict__ row,
                      const int* __restrict__ col, int n_edges, int n_nodes) {
    int e = blockIdx.x * blockDim.x + threadIdx.x;
    if (e >= n_edges) return;
    unsigned r = (unsigned)__ldg(&row[e]);
    unsigned t = (unsigned)__ldg(&col[e]);
    if (r >= (unsigned)n_nodes || t >= (unsigned)n_nodes) return;
    float2 v = *reinterpret_cast<const float2*>(&d_g2[r * 2]);
    float* dst = &d_agg2[t * 2];
    asm volatile("red.global.add.v2.f32 [%0], {%1,%2};"
                 :: "l"(dst), "f"(v.x), "f"(v.y)
                 : "memory");
}

// Epilogue-2: z = dinv*(agg2+g2)+b2, then log_softmax over 2 classes.
__global__ void k_out(const float* __restrict__ b2,
                      float* __restrict__ out, int n) {
    int i = blockIdx.x * blockDim.x + threadIdx.x;
    if (i >= n) return;
    float dinv = d_dinv[i];
    float2 a = *reinterpret_cast<const float2*>(&d_agg2[i * 2]);
    float2 g = *reinterpret_cast<const float2*>(&d_g2[i * 2]);
    float z0 = dinv * (a.x + g.x) + __ldg(&b2[0]);
    float z1 = dinv * (a.y + g.y) + __ldg(&b2[1]);
    float m = fmaxf(z0, z1);
    float lse = m + logf(expf(z0 - m) + expf(z1 - m));
    out[i * 2 + 0] = z0 - lse;
    out[i * 2 + 1] = z1 - lse;
}

// ---- launch ----

extern "C" void kernel_launch(void* const* d_in, const int* in_sizes, int n_in,
                              void* d_out, int out_size) {
    const float* x  = (const float*)d_in[0];
    const int*   ei = (const int*)d_in[1];
    const float* W1 = (const float*)d_in[2];
    const float* b1 = (const float*)d_in[3];
    const float* W2 = (const float*)d_in[4];
    const float* b2 = (const float*)d_in[5];
    float*       out = (float*)d_out;

    int n_nodes = in_sizes[0] / F_IN;
    int n_edges = in_sizes[1] / 2;
    const int* row = ei;             // sources
    const int* col = ei + n_edges;   // targets

    const int B = 256;
    int gn = (n_nodes + B - 1) / B;
    int ge = (n_edges + B - 1) / B;
    long long tot4 = 4LL * n_edges;
    int ge4 = (int)((tot4 + B - 1) / B);

    k_zero <<<gn, B>>>(n_nodes);
    k_deg  <<<ge, B>>>(col, n_edges, n_nodes);
    k_node1<<<gn, B>>>(x, W1, n_nodes);
    k_sc1  <<<ge4, B>>>(row, col, n_edges, n_nodes);
    k_node2<<<gn, B>>>(b1, W2, n_nodes);
    k_sc2  <<<ge, B>>>(row, col, n_edges, n_nodes);
    k_out  <<<gn, B>>>(b2, out, n_nodes);
}